// round 2
// baseline (speedup 1.0000x reference)
#include <cuda_runtime.h>
#include <math.h>

#define N_   4
#define T_   2048
#define D_   1024
#define H_   16
#define DH_  64
#define CAP_ 30.0f
#define EPS_ 1e-5f
#define ROWS_ (N_ * T_)          // 8192

// ---------------- scratch (device globals: allocation-free) ----------------
__device__ float g_h[(size_t)ROWS_ * D_];            // LN output, reused as attention output
__device__ float g_q[(size_t)ROWS_ * H_ * DH_];
__device__ float g_k[(size_t)ROWS_ * H_ * DH_];
__device__ float g_v[(size_t)ROWS_ * H_ * DH_];

// ---------------- LayerNorm: one block per row ----------------
__global__ void ln_kernel(const float* __restrict__ x, const float* __restrict__ gw,
                          const float* __restrict__ bw, float* __restrict__ out) {
    __shared__ float red[8];
    __shared__ float stat[2];
    const int row = blockIdx.x;
    const int t = threadIdx.x;            // 256 threads
    const float* xr = x + (size_t)row * D_;
    float v[4];
    float s = 0.f;
#pragma unroll
    for (int i = 0; i < 4; i++) { v[i] = xr[t + i * 256]; s += v[i]; }
#pragma unroll
    for (int o = 16; o; o >>= 1) s += __shfl_xor_sync(0xffffffffu, s, o);
    if ((t & 31) == 0) red[t >> 5] = s;
    __syncthreads();
    if (t == 0) {
        float tot = 0.f;
#pragma unroll
        for (int i = 0; i < 8; i++) tot += red[i];
        stat[0] = tot * (1.f / D_);
    }
    __syncthreads();
    const float mean = stat[0];
    float ss = 0.f;
#pragma unroll
    for (int i = 0; i < 4; i++) { float d = v[i] - mean; ss += d * d; }
#pragma unroll
    for (int o = 16; o; o >>= 1) ss += __shfl_xor_sync(0xffffffffu, ss, o);
    if ((t & 31) == 0) red[t >> 5] = ss;
    __syncthreads();
    if (t == 0) {
        float tot = 0.f;
#pragma unroll
        for (int i = 0; i < 8; i++) tot += red[i];
        stat[1] = rsqrtf(tot * (1.f / D_) + EPS_);
    }
    __syncthreads();
    const float rs = stat[1];
    float* orow = out + (size_t)row * D_;
#pragma unroll
    for (int i = 0; i < 4; i++) {
        int c = t + i * 256;
        orow[c] = (v[i] - mean) * rs * gw[c] + bw[c];
    }
}

// ---------------- SGEMM: C[M,Nn] = A[M,K] * B[K,Nn] + bias ----------------
// 64x64x64 tiles, 128 threads, 4x8 microtile per thread.
// A tile stored k-major (transposed) in smem so inner loop is LDS.128-friendly.
__global__ void gemm_bias_kernel(const float* __restrict__ A, const float* __restrict__ B,
                                 const float* __restrict__ bias, float* __restrict__ C,
                                 int M, int Nn, int K) {
    __shared__ float Ast[64][68];   // [k][m]
    __shared__ float Bs[64][68];    // [k][n]
    const int m0 = blockIdx.y * 64;
    const int n0 = blockIdx.x * 64;
    const int tid = threadIdx.x;
    const int tr = tid >> 3;        // 0..15 -> 4 rows
    const int tc = tid & 7;         // 0..7  -> 8 cols

    float acc[4][8];
#pragma unroll
    for (int i = 0; i < 4; i++)
#pragma unroll
        for (int j = 0; j < 8; j++) acc[i][j] = 0.f;

    for (int k0 = 0; k0 < K; k0 += 64) {
#pragma unroll
        for (int i = 0; i < 8; i++) {
            int lin = tid + i * 128;          // 0..1023
            int r = lin >> 4;                 // tile row 0..63
            int c4 = (lin & 15) * 4;          // tile col 0..60
            float4 av = *(const float4*)(A + (size_t)(m0 + r) * K + k0 + c4);
            Ast[c4 + 0][r] = av.x;
            Ast[c4 + 1][r] = av.y;
            Ast[c4 + 2][r] = av.z;
            Ast[c4 + 3][r] = av.w;
            float4 bv = *(const float4*)(B + (size_t)(k0 + r) * Nn + n0 + c4);
            *(float4*)&Bs[r][c4] = bv;
        }
        __syncthreads();
#pragma unroll 8
        for (int k = 0; k < 64; k++) {
            float4 a4 = *(float4*)&Ast[k][tr * 4];
            float4 b0 = *(float4*)&Bs[k][tc * 8];
            float4 b1 = *(float4*)&Bs[k][tc * 8 + 4];
            float a[4] = {a4.x, a4.y, a4.z, a4.w};
            float bb[8] = {b0.x, b0.y, b0.z, b0.w, b1.x, b1.y, b1.z, b1.w};
#pragma unroll
            for (int i = 0; i < 4; i++)
#pragma unroll
                for (int j = 0; j < 8; j++)
                    acc[i][j] = fmaf(a[i], bb[j], acc[i][j]);
        }
        __syncthreads();
    }

#pragma unroll
    for (int i = 0; i < 4; i++) {
        size_t rbase = (size_t)(m0 + tr * 4 + i) * Nn + n0 + tc * 8;
        float4 c0, c1;
        c0.x = acc[i][0] + bias[n0 + tc * 8 + 0];
        c0.y = acc[i][1] + bias[n0 + tc * 8 + 1];
        c0.z = acc[i][2] + bias[n0 + tc * 8 + 2];
        c0.w = acc[i][3] + bias[n0 + tc * 8 + 3];
        c1.x = acc[i][4] + bias[n0 + tc * 8 + 4];
        c1.y = acc[i][5] + bias[n0 + tc * 8 + 5];
        c1.z = acc[i][6] + bias[n0 + tc * 8 + 6];
        c1.w = acc[i][7] + bias[n0 + tc * 8 + 7];
        *(float4*)(C + rbase) = c0;
        *(float4*)(C + rbase + 4) = c1;
    }
}

// ---------------- RoPE on q and k in place ----------------
// layout [b][t][h][d], rotate pairs (2p, 2p+1)
__global__ void rope_kernel(float* __restrict__ q, float* __restrict__ k) {
    int idx = blockIdx.x * blockDim.x + threadIdx.x;   // 2^22 threads
    int p = idx & 31;
    int h = (idx >> 5) & (H_ - 1);
    int t = (idx >> 9) & (T_ - 1);
    int b = idx >> 20;
    // inv_freq in double to track the fp32 reference closely
    double e = -((double)(2 * p) / 64.0) * 9.210340371976184;  // ln(10000)
    float inv = (float)exp(e);
    float ang = (float)t * inv;
    float sn, cs;
    sincosf(ang, &sn, &cs);
    size_t base = (((size_t)b * T_ + t) * H_ + h) * DH_ + 2 * p;
    float x1 = q[base], x2 = q[base + 1];
    q[base]     = x1 * cs - x2 * sn;
    q[base + 1] = x1 * sn + x2 * cs;
    x1 = k[base]; x2 = k[base + 1];
    k[base]     = x1 * cs - x2 * sn;
    k[base + 1] = x1 * sn + x2 * cs;
}

// ---------------- Flash attention, fp32, 64x64 tiles ----------------
#define ATT_SMEM (4 * 64 * 68 * 4)

__global__ void attn_kernel(const float* __restrict__ Q, const float* __restrict__ K,
                            const float* __restrict__ V, const int* __restrict__ lens,
                            float* __restrict__ O) {
    extern __shared__ float sm[];
    float (*Qs)[68] = (float(*)[68])sm;
    float (*Ks)[68] = (float(*)[68])(sm + 64 * 68);
    float (*Vs)[68] = (float(*)[68])(sm + 2 * 64 * 68);
    float (*Ps)[68] = (float(*)[68])(sm + 3 * 64 * 68);

    const int q0 = blockIdx.x * 64;
    const int h  = blockIdx.y;
    const int b  = blockIdx.z;
    const int len = lens[b];
    const int tid = threadIdx.x;
    const int tr = tid >> 3, tc = tid & 7;

#pragma unroll
    for (int i = 0; i < 8; i++) {
        int lin = tid + i * 128;
        int r = lin >> 4, c4 = (lin & 15) * 4;
        *(float4*)&Qs[r][c4] =
            *(const float4*)(Q + (((size_t)b * T_ + q0 + r) * H_ + h) * DH_ + c4);
    }

    float m_i[4], l_i[4], o[4][8];
#pragma unroll
    for (int i = 0; i < 4; i++) {
        m_i[i] = -INFINITY; l_i[i] = 0.f;
#pragma unroll
        for (int j = 0; j < 8; j++) o[i][j] = 0.f;
    }

    const int kend = min(q0 + 64, len);   // exclusive bound on tile starts
    __syncthreads();

    for (int kn0 = 0; kn0 < kend; kn0 += 64) {
#pragma unroll
        for (int i = 0; i < 8; i++) {
            int lin = tid + i * 128;
            int r = lin >> 4, c4 = (lin & 15) * 4;
            size_t gk = (((size_t)b * T_ + kn0 + r) * H_ + h) * DH_ + c4;
            *(float4*)&Ks[r][c4] = *(const float4*)(K + gk);
            *(float4*)&Vs[r][c4] = *(const float4*)(V + gk);
        }
        __syncthreads();

        float s[4][8];
#pragma unroll
        for (int i = 0; i < 4; i++)
#pragma unroll
            for (int j = 0; j < 8; j++) s[i][j] = 0.f;

#pragma unroll 8
        for (int d = 0; d < 64; d++) {
            float a[4], kk[8];
#pragma unroll
            for (int i = 0; i < 4; i++) a[i] = Qs[tr * 4 + i][d];
#pragma unroll
            for (int j = 0; j < 8; j++) kk[j] = Ks[tc * 8 + j][d];
#pragma unroll
            for (int i = 0; i < 4; i++)
#pragma unroll
                for (int j = 0; j < 8; j++)
                    s[i][j] = fmaf(a[i], kk[j], s[i][j]);
        }

        // scale, tanh-cap, mask
#pragma unroll
        for (int i = 0; i < 4; i++) {
            int qi = q0 + tr * 4 + i;
#pragma unroll
            for (int j = 0; j < 8; j++) {
                int kj = kn0 + tc * 8 + j;
                float sv = s[i][j] * 0.125f;
                sv = CAP_ * tanhf(sv * (1.f / CAP_));
                if (kj > qi || kj >= len) sv = -INFINITY;
                s[i][j] = sv;
            }
        }

        // online softmax (row = 8-lane group)
#pragma unroll
        for (int i = 0; i < 4; i++) {
            float mt = s[i][0];
#pragma unroll
            for (int j = 1; j < 8; j++) mt = fmaxf(mt, s[i][j]);
            mt = fmaxf(mt, __shfl_xor_sync(0xffffffffu, mt, 1));
            mt = fmaxf(mt, __shfl_xor_sync(0xffffffffu, mt, 2));
            mt = fmaxf(mt, __shfl_xor_sync(0xffffffffu, mt, 4));
            float mnew = fmaxf(m_i[i], mt);
            float alpha = (mnew == -INFINITY) ? 1.f : __expf(m_i[i] - mnew);
            float rs = 0.f;
#pragma unroll
            for (int j = 0; j < 8; j++) {
                float p = (s[i][j] == -INFINITY) ? 0.f : __expf(s[i][j] - mnew);
                Ps[tr * 4 + i][tc * 8 + j] = p;
                rs += p;
            }
            rs += __shfl_xor_sync(0xffffffffu, rs, 1);
            rs += __shfl_xor_sync(0xffffffffu, rs, 2);
            rs += __shfl_xor_sync(0xffffffffu, rs, 4);
            l_i[i] = l_i[i] * alpha + rs;
            m_i[i] = mnew;
#pragma unroll
            for (int j = 0; j < 8; j++) o[i][j] *= alpha;
        }
        __syncthreads();

        // O += P * V
#pragma unroll 8
        for (int j = 0; j < 64; j++) {
            float pr[4];
#pragma unroll
            for (int i = 0; i < 4; i++) pr[i] = Ps[tr * 4 + i][j];
            float4 v0 = *(float4*)&Vs[j][tc * 8];
            float4 v1 = *(float4*)&Vs[j][tc * 8 + 4];
            float vv[8] = {v0.x, v0.y, v0.z, v0.w, v1.x, v1.y, v1.z, v1.w};
#pragma unroll
            for (int i = 0; i < 4; i++)
#pragma unroll
                for (int jj = 0; jj < 8; jj++)
                    o[i][jj] = fmaf(pr[i], vv[jj], o[i][jj]);
        }
        __syncthreads();
    }

#pragma unroll
    for (int i = 0; i < 4; i++) {
        float inv = (l_i[i] > 0.f) ? (1.f / l_i[i]) : 0.f;
        int t = q0 + tr * 4 + i;
        size_t base = (((size_t)b * T_ + t) * H_ + h) * DH_ + tc * 8;
#pragma unroll
        for (int j = 0; j < 8; j++)
            O[base + j] = o[i][j] * inv;
    }
}

// ---------------- launcher ----------------
extern "C" void kernel_launch(void* const* d_in, const int* in_sizes, int n_in,
                              void* d_out, int out_size) {
    const float* x    = (const float*)d_in[0];
    const float* ln_g = (const float*)d_in[1];
    const float* ln_b = (const float*)d_in[2];
    const float* Wq   = (const float*)d_in[3];
    const float* bq   = (const float*)d_in[4];
    const float* Wk   = (const float*)d_in[5];
    const float* bk   = (const float*)d_in[6];
    const float* Wv   = (const float*)d_in[7];
    const float* bv   = (const float*)d_in[8];
    const float* Wo   = (const float*)d_in[9];
    const float* bo   = (const float*)d_in[10];
    const int*  lens  = (const int*)d_in[13];
    float* out = (float*)d_out;

    float *h_, *q_, *k_, *v_;
    cudaGetSymbolAddress((void**)&h_, g_h);
    cudaGetSymbolAddress((void**)&q_, g_q);
    cudaGetSymbolAddress((void**)&k_, g_k);
    cudaGetSymbolAddress((void**)&v_, g_v);

    ln_kernel<<<ROWS_, 256>>>(x, ln_g, ln_b, h_);

    dim3 gg(D_ / 64, ROWS_ / 64);   // (16, 128)
    gemm_bias_kernel<<<gg, 128>>>(h_, Wq, bq, q_, ROWS_, H_ * DH_, D_);
    gemm_bias_kernel<<<gg, 128>>>(h_, Wk, bk, k_, ROWS_, H_ * DH_, D_);
    gemm_bias_kernel<<<gg, 128>>>(h_, Wv, bv, v_, ROWS_, H_ * DH_, D_);

    rope_kernel<<<(N_ * T_ * H_ * 32) / 256, 256>>>(q_, k_);

    cudaFuncSetAttribute(attn_kernel, cudaFuncAttributeMaxDynamicSharedMemorySize, ATT_SMEM);
    // attention output written into g_h (h no longer needed)
    attn_kernel<<<dim3(T_ / 64, H_, N_), 128, ATT_SMEM>>>(q_, k_, v_, lens, h_);

    gemm_bias_kernel<<<gg, 128>>>(h_, Wo, bo, out, ROWS_, D_, H_ * DH_);
}